// round 4
// baseline (speedup 1.0000x reference)
#include <cuda_runtime.h>
#include <cstdint>

typedef unsigned long long ull;

#define THREADS 512
#define OUTF 11008
#define INF 4096
#define NBLK 688                    /* OUTF/16 row-blocks, one per CTA */

/* LUT as two 4B planes, each entry replicated 32x (one copy per lane):
   plane0[e][l] at byte e*128 + l*4, plane1 at +65536.
   bank(access) = lane exactly -> conflict-free under any wavefront split. */
#define SMEM_LUT_BYTES (512*32*4*2)     /* 131072 */
#define SMEM_RED_BYTES (16*64*4)        /* 4KB */
#define SMEM_TOTAL (SMEM_LUT_BYTES + SMEM_RED_BYTES)
#define PLANE1_OFF 65536

__device__ __forceinline__ uint32_t smem_u32(const void* p) {
    uint32_t a;
    asm("{ .reg .u64 t; cvta.to.shared.u64 t, %1; cvt.u32.u64 %0, t; }"
        : "=r"(a) : "l"(p));
    return a;
}
__device__ __forceinline__ ull pack2(float lo, float hi) {
    ull r; asm("mov.b64 %0, {%1,%2};" : "=l"(r) : "f"(lo), "f"(hi)); return r;
}
__device__ __forceinline__ ull pack2u(uint32_t lo, uint32_t hi) {
    ull r; asm("mov.b64 %0, {%1,%2};" : "=l"(r) : "r"(lo), "r"(hi)); return r;
}
__device__ __forceinline__ void fma2(ull& acc, ull a, ull b) {
    asm("fma.rn.f32x2 %0, %1, %2, %0;" : "+l"(acc) : "l"(a), "l"(b));
}
__device__ __forceinline__ float sum2(ull v) {
    float a, b; asm("mov.b64 {%0,%1}, %2;" : "=f"(a), "=f"(b) : "l"(v));
    return a + b;
}
__device__ __forceinline__ uint32_t lds32(uint32_t addr) {
    uint32_t v; asm("ld.shared.b32 %0, [%1];" : "=r"(v) : "r"(addr));
    return v;
}
__device__ __forceinline__ uint32_t lds32_p1(uint32_t addr) {  /* plane 1 */
    uint32_t v; asm("ld.shared.b32 %0, [%1+65536];" : "=r"(v) : "r"(addr));
    return v;
}

__global__ void __launch_bounds__(THREADS, 1)
tcq_kernel(const float* __restrict__ inp,
           const int* __restrict__ trellis1,
           const int* __restrict__ trellis2,
           const float* __restrict__ tlut,
           float* __restrict__ out)
{
    extern __shared__ char smem_raw[];
    float* red = (float*)(smem_raw + SMEM_LUT_BYTES);

    const int tid  = threadIdx.x;
    const int lane = tid & 31;
    const int warp = tid >> 5;
    const int mo   = blockIdx.x;
    const int ko   = tid & 255;     // trellis block within mo
    const int half = tid >> 8;      // 0: word 2tx (cols 0-7), 1: word 2tx+1 (cols 8-15)

    // ---- trellis block ko: 32 words; pack per row p[tx]=(w[2tx]<<16)|w[2tx+1]
    const int4* tq = (ko < 128)
        ? (const int4*)(trellis1 + (size_t)(mo * 128 + ko) * 32)
        : (const int4*)(trellis2 + (size_t)(mo * 128 + (ko - 128)) * 32);
    uint32_t p[16];
#pragma unroll
    for (int q = 0; q < 8; q++) {
        const int4 v = tq[q];
        p[2 * q + 0] = (((uint32_t)v.x & 0xFFFFu) << 16) | ((uint32_t)v.y & 0xFFFFu);
        p[2 * q + 1] = (((uint32_t)v.z & 0xFFFFu) << 16) | ((uint32_t)v.w & 0xFFFFu);
    }

    // ---- stage split-plane LUT: warp w handles entries e = w + 16j;
    //      per entry: broadcast LDG.64, two fully-coalesced STS.32. ----
    {
        const float2* src = (const float2*)tlut;
        float* pl0 = (float*)smem_raw;
        float* pl1 = (float*)(smem_raw + PLANE1_OFF);
#pragma unroll 4
        for (int e = warp; e < 512; e += 16) {
            const float2 v = src[e];
            pl0[e * 32 + lane] = v.x;
            pl1[e * 32 + lane] = v.y;
        }
    }

    // ---- x for this thread's 8 global columns [ko*16+half*8, +8), 4 batches
    ull x2[4][4];
    {
        const float4* xv = (const float4*)inp;
        const int cb = ko * 4 + half * 2;
#pragma unroll
        for (int b = 0; b < 4; b++) {
#pragma unroll
            for (int q = 0; q < 2; q++) {
                float4 v = xv[b * (INF / 4) + cb + q];
                x2[b][2 * q + 0] = pack2(v.x, v.y);
                x2[b][2 * q + 1] = pack2(v.z, v.w);
            }
        }
    }

    __syncthreads();

    const uint32_t lut_lane = smem_u32(smem_raw) + (uint32_t)lane * 4u;

    // Decode: idx[s] = 9-bit window ending at nibble s of the big-endian word
    // stream (the L=16 state recurrence collapses to a sliding window).
    // half=1 ctx for row tx is p[tx]; half=0 ctx is funnel(p[tx], p[tx-1], 16).
    uint32_t pv = 0;

#pragma unroll
    for (int ph = 0; ph < 4; ph++) {            // rows ph*4 .. ph*4+3
        ull acc[4][4];
#pragma unroll
        for (int r = 0; r < 4; r++)
#pragma unroll
            for (int b = 0; b < 4; b++) acc[r][b] = 0ull;

#pragma unroll
        for (int r = 0; r < 4; r++) {
            const int tx = ph * 4 + r;
            const uint32_t ctx = half ? p[tx]
                                      : __funnelshift_l(p[tx], pv, 16);
            pv = p[tx];

            // addresses for the 4 steps, then all 8 loads in flight
            uint32_t a[4], lo[4], hi[4];
#pragma unroll
            for (int t = 0; t < 4; t++)
                a[t] = lut_lane + ((ctx >> (12 - 4 * t)) & 0x1FFu) * 128u;
#pragma unroll
            for (int t = 0; t < 4; t++) { lo[t] = lds32(a[t]); hi[t] = lds32_p1(a[t]); }

#pragma unroll
            for (int t = 0; t < 4; t++) {
                const ull w2 = pack2u(lo[t], hi[t]);
                fma2(acc[r][0], w2, x2[0][t]);
                fma2(acc[r][1], w2, x2[1][t]);
                fma2(acc[r][2], w2, x2[2][t]);
                fma2(acc[r][3], w2, x2[3][t]);
            }
        }

        // collapse packed partials, then value-rotating warp reduction:
        // 16 sums over 32 lanes -> 1 per lane (15 shfl) + closing xor-16 add.
        float v[16];
#pragma unroll
        for (int r = 0; r < 4; r++)
#pragma unroll
            for (int b = 0; b < 4; b++) v[r * 4 + b] = sum2(acc[r][b]);

#define ROUND(S, N) { _Pragma("unroll")                                   \
        for (int i = 0; i < (N) / 2; i++) {                               \
            const bool hi2 = (lane & (S)) != 0;                           \
            const float snd = hi2 ? v[i] : v[i + (N) / 2];                \
            const float kp  = hi2 ? v[i + (N) / 2] : v[i];                \
            v[i] = kp + __shfl_xor_sync(0xffffffffu, snd, (S));           \
        } }
        ROUND(1, 16) ROUND(2, 8) ROUND(4, 4) ROUND(8, 2)
#undef ROUND
        v[0] += __shfl_xor_sync(0xffffffffu, v[0], 16);

        // lane l (l<16) holds value index bitrev4(l) = r*4+b of this phase
        const int oi = ((lane & 1) << 3) | ((lane & 2) << 1)
                     | ((lane & 4) >> 1) | ((lane & 8) >> 3);
        if (lane < 16) red[warp * 64 + ph * 16 + oi] = v[0];
    }

    __syncthreads();

    // cross-warp combine: 64 outputs (16 rows x 4 batches), 16 warps each
    if (tid < 64) {
        float s = 0.f;
#pragma unroll
        for (int w = 0; w < 16; w++) s += red[w * 64 + tid];
        const int phx = tid >> 4;         // tid = ph*16 + r*4 + b
        const int r   = (tid >> 2) & 3;
        const int b   = tid & 3;
        out[(size_t)b * OUTF + mo * 16 + phx * 4 + r] = s;
    }
}

extern "C" void kernel_launch(void* const* d_in, const int* in_sizes, int n_in,
                              void* d_out, int out_size) {
    const float* inp  = (const float*)d_in[0];
    const int*   t1   = (const int*)d_in[1];
    const int*   t2   = (const int*)d_in[2];
    const float* tlut = (const float*)d_in[3];
    float*       out  = (float*)d_out;

    cudaFuncSetAttribute(tcq_kernel,
                         cudaFuncAttributeMaxDynamicSharedMemorySize,
                         SMEM_TOTAL);
    tcq_kernel<<<NBLK, THREADS, SMEM_TOTAL>>>(inp, t1, t2, tlut, out);
}

// round 5
// speedup vs baseline: 1.4710x; 1.4710x over previous
#include <cuda_runtime.h>
#include <cstdint>

typedef unsigned long long ull;

#define THREADS 512
#define OUTF 11008
#define INF 4096
#define NBLK 688                    /* OUTF/16 row-blocks, one per CTA */

#define SMEM_LUT_BYTES (512*16*8)   /* 64KB: LUT replicated 16x, interleaved */
#define SMEM_TRE_BYTES (2048*16)    /* 32KB: 256 blocks x 8 int4, swizzled   */
#define SMEM_X_BYTES   (4096*16)    /* 64KB: full x, float4 flat, swizzled   */
#define SMEM_RED_BYTES (16*64*4)    /* 4KB */
#define TRE_OFF SMEM_LUT_BYTES
#define X_OFF   (TRE_OFF + SMEM_TRE_BYTES)
#define RED_OFF (X_OFF + SMEM_X_BYTES)
#define SMEM_TOTAL (RED_OFF + SMEM_RED_BYTES)   /* 167936 */

__device__ __forceinline__ uint32_t smem_u32(const void* p) {
    uint32_t a;
    asm("{ .reg .u64 t; cvta.to.shared.u64 t, %1; cvt.u32.u64 %0, t; }"
        : "=r"(a) : "l"(p));
    return a;
}
__device__ __forceinline__ ull pack2(float lo, float hi) {
    ull r; asm("mov.b64 %0, {%1,%2};" : "=l"(r) : "f"(lo), "f"(hi)); return r;
}
__device__ __forceinline__ void fma2(ull& acc, ull a, ull b) {
    asm("fma.rn.f32x2 %0, %1, %2, %0;" : "+l"(acc) : "l"(a), "l"(b));
}
__device__ __forceinline__ float sum2(ull v) {
    float a, b; asm("mov.b64 {%0,%1}, %2;" : "=f"(a), "=f"(b) : "l"(v));
    return a + b;
}
__device__ __forceinline__ ull lds64(uint32_t addr) {
    ull v; asm("ld.shared.b64 %0, [%1];" : "=l"(v) : "r"(addr));
    return v;
}
/* 16B-granularity XOR swizzle: conflict-free for both the coalesced store
   side and the strided per-thread read side (verified per quarter-warp). */
__device__ __forceinline__ int swz(int f) { return f ^ ((f >> 3) & 7); }

__global__ void __launch_bounds__(THREADS, 1)
tcq_kernel(const float* __restrict__ inp,
           const int* __restrict__ trellis1,
           const int* __restrict__ trellis2,
           const float* __restrict__ tlut,
           float* __restrict__ out)
{
    extern __shared__ char smem_raw[];
    ull*    lut = (ull*)smem_raw;
    int4*   tre = (int4*)(smem_raw + TRE_OFF);
    float4* xs  = (float4*)(smem_raw + X_OFF);
    float*  red = (float*)(smem_raw + RED_OFF);

    const int tid  = threadIdx.x;
    const int lane = tid & 31;
    const int warp = tid >> 5;
    const int mo   = blockIdx.x;
    const int ko   = tid & 255;     // trellis block within mo
    const int half = tid >> 8;      // 0: word 2tx (cols 0-7), 1: word 2tx+1 (cols 8-15)

    // ======== coalesced staging (all LDG fully coalesced) ========
    {   // LUT replicated 16x interleaved: entry e replica r at ull idx e*16+r
        const ull* src = (const ull*)tlut;
#pragma unroll
        for (int k = tid; k < 8192; k += THREADS)
            lut[k] = src[k >> 4];               // broadcast LDG, coalesced STS
    }
    {   // trellis: 2048 int4 flat (t1 then t2), swizzled store
        const int4* t1v = (const int4*)trellis1 + (size_t)mo * 1024;
        const int4* t2v = (const int4*)trellis2 + (size_t)mo * 1024;
#pragma unroll
        for (int f = tid; f < 2048; f += THREADS) {
            const int4 v = (f < 1024) ? t1v[f] : t2v[f - 1024];
            tre[swz(f)] = v;
        }
    }
    {   // x: 4096 float4 flat [b*1024 + c4], swizzled store
        const float4* xv = (const float4*)inp;
#pragma unroll
        for (int f = tid; f < 4096; f += THREADS)
            xs[swz(f)] = xv[f];
    }
    __syncthreads();

    // ======== per-thread gathers from smem (conflict-free LDS.128) ========
    // trellis block ko, words packed per row: p[tx] = (w[2tx]<<16)|w[2tx+1]
    uint32_t p[16];
#pragma unroll
    for (int q = 0; q < 8; q++) {
        const int4 v = tre[ko * 8 + (q ^ (ko & 7))];
        p[2 * q + 0] = (((uint32_t)v.x & 0xFFFFu) << 16) | ((uint32_t)v.y & 0xFFFFu);
        p[2 * q + 1] = (((uint32_t)v.z & 0xFFFFu) << 16) | ((uint32_t)v.w & 0xFFFFu);
    }
    // x for this thread's 8 global columns [ko*16+half*8, +8), 4 batches
    ull x2[4][4];
#pragma unroll
    for (int b = 0; b < 4; b++) {
#pragma unroll
        for (int q = 0; q < 2; q++) {
            const int f = b * 1024 + ko * 4 + half * 2 + q;
            const float4 v = xs[swz(f)];
            x2[b][2 * q + 0] = pack2(v.x, v.y);
            x2[b][2 * q + 1] = pack2(v.z, v.w);
        }
    }

    const uint32_t lut_lane = smem_u32(smem_raw) + (uint32_t)(lane & 15) * 8u;

    // Decode: idx[s] = 9-bit window ending at nibble s of the big-endian word
    // stream (L=16 state recurrence collapses to a sliding window).
    // half=1 ctx for row tx is p[tx]; half=0 ctx is funnel(p[tx], p[tx-1], 16).
    uint32_t pv = 0;

#pragma unroll
    for (int ph = 0; ph < 4; ph++) {            // rows ph*4 .. ph*4+3
        ull acc[4][4];
#pragma unroll
        for (int r = 0; r < 4; r++)
#pragma unroll
            for (int b = 0; b < 4; b++) acc[r][b] = 0ull;

#pragma unroll
        for (int r = 0; r < 4; r++) {
            const int tx = ph * 4 + r;
            const uint32_t ctx = half ? p[tx]
                                      : __funnelshift_l(p[tx], pv, 16);
            pv = p[tx];
#pragma unroll
            for (int t = 0; t < 4; t++) {
                const uint32_t idx = (ctx >> (12 - 4 * t)) & 0x1FFu;
                const ull w2 = lds64(lut_lane + idx * 128u);
                fma2(acc[r][0], w2, x2[0][t]);
                fma2(acc[r][1], w2, x2[1][t]);
                fma2(acc[r][2], w2, x2[2][t]);
                fma2(acc[r][3], w2, x2[3][t]);
            }
        }

        // collapse packed partials, then value-rotating warp reduction:
        // 16 sums over 32 lanes -> 1 per lane (15 shfl) + closing xor-16 add.
        float v[16];
#pragma unroll
        for (int r = 0; r < 4; r++)
#pragma unroll
            for (int b = 0; b < 4; b++) v[r * 4 + b] = sum2(acc[r][b]);

#define ROUND(S, N) { _Pragma("unroll")                                   \
        for (int i = 0; i < (N) / 2; i++) {                               \
            const bool hi2 = (lane & (S)) != 0;                           \
            const float snd = hi2 ? v[i] : v[i + (N) / 2];                \
            const float kp  = hi2 ? v[i + (N) / 2] : v[i];                \
            v[i] = kp + __shfl_xor_sync(0xffffffffu, snd, (S));           \
        } }
        ROUND(1, 16) ROUND(2, 8) ROUND(4, 4) ROUND(8, 2)
#undef ROUND
        v[0] += __shfl_xor_sync(0xffffffffu, v[0], 16);

        // lane l (l<16) holds value index bitrev4(l) = r*4+b of this phase
        const int oi = ((lane & 1) << 3) | ((lane & 2) << 1)
                     | ((lane & 4) >> 1) | ((lane & 8) >> 3);
        if (lane < 16) red[warp * 64 + ph * 16 + oi] = v[0];
    }

    __syncthreads();

    // cross-warp combine: 64 outputs (16 rows x 4 batches), 16 warps each
    if (tid < 64) {
        float s = 0.f;
#pragma unroll
        for (int w = 0; w < 16; w++) s += red[w * 64 + tid];
        const int phx = tid >> 4;         // tid = ph*16 + r*4 + b
        const int r   = (tid >> 2) & 3;
        const int b   = tid & 3;
        out[(size_t)b * OUTF + mo * 16 + phx * 4 + r] = s;
    }
}

extern "C" void kernel_launch(void* const* d_in, const int* in_sizes, int n_in,
                              void* d_out, int out_size) {
    const float* inp  = (const float*)d_in[0];
    const int*   t1   = (const int*)d_in[1];
    const int*   t2   = (const int*)d_in[2];
    const float* tlut = (const float*)d_in[3];
    float*       out  = (float*)d_out;

    cudaFuncSetAttribute(tcq_kernel,
                         cudaFuncAttributeMaxDynamicSharedMemorySize,
                         SMEM_TOTAL);
    tcq_kernel<<<NBLK, THREADS, SMEM_TOTAL>>>(inp, t1, t2, tlut, out);
}

// round 6
// speedup vs baseline: 1.4886x; 1.0120x over previous
#include <cuda_runtime.h>
#include <cstdint>

typedef unsigned long long ull;

#define THREADS 512
#define OUTF 11008
#define INF 4096
#define NBLK 688                    /* OUTF/16 row-blocks, one per CTA */

#define SMEM_LUT_BYTES (512*16*8)   /* 64KB: LUT replicated 16x, interleaved */
#define SMEM_TRE_BYTES (2048*16)    /* 32KB: 256 blocks x 8 int4, swizzled   */
#define SMEM_X_BYTES   (4096*16)    /* 64KB: full x, float4 flat, swizzled   */
#define SMEM_RED_BYTES (16*64*4)    /* 4KB */
#define TRE_OFF SMEM_LUT_BYTES
#define X_OFF   (TRE_OFF + SMEM_TRE_BYTES)
#define RED_OFF (X_OFF + SMEM_X_BYTES)
#define SMEM_TOTAL (RED_OFF + SMEM_RED_BYTES)   /* 167936 */

__device__ __forceinline__ uint32_t smem_u32(const void* p) {
    uint32_t a;
    asm("{ .reg .u64 t; cvta.to.shared.u64 t, %1; cvt.u32.u64 %0, t; }"
        : "=r"(a) : "l"(p));
    return a;
}
__device__ __forceinline__ ull pack2(float lo, float hi) {
    ull r; asm("mov.b64 %0, {%1,%2};" : "=l"(r) : "f"(lo), "f"(hi)); return r;
}
__device__ __forceinline__ void fma2(ull& acc, ull a, ull b) {
    asm("fma.rn.f32x2 %0, %1, %2, %0;" : "+l"(acc) : "l"(a), "l"(b));
}
__device__ __forceinline__ float sum2(ull v) {
    float a, b; asm("mov.b64 {%0,%1}, %2;" : "=f"(a), "=f"(b) : "l"(v));
    return a + b;
}
__device__ __forceinline__ ull lds64(uint32_t addr) {
    ull v; asm("ld.shared.b64 %0, [%1];" : "=l"(v) : "r"(addr));
    return v;
}
/* 16B-granularity XOR swizzle: conflict-free for both the coalesced store
   side and the strided per-thread read side. */
__device__ __forceinline__ int swz(int f) { return f ^ ((f >> 3) & 7); }

__global__ void __launch_bounds__(THREADS, 1)
tcq_kernel(const float* __restrict__ inp,
           const int* __restrict__ trellis1,
           const int* __restrict__ trellis2,
           const float* __restrict__ tlut,
           float* __restrict__ out)
{
    extern __shared__ char smem_raw[];
    ull*    lut = (ull*)smem_raw;
    int4*   tre = (int4*)(smem_raw + TRE_OFF);
    float4* xs  = (float4*)(smem_raw + X_OFF);
    float*  red = (float*)(smem_raw + RED_OFF);

    const int tid  = threadIdx.x;
    const int lane = tid & 31;
    const int warp = tid >> 5;
    const int mo   = blockIdx.x;
    const int ko   = tid & 255;     // trellis block within mo
    const int half = tid >> 8;      // 0: word 2tx (cols 0-7), 1: word 2tx+1 (cols 8-15)

    // ======== coalesced staging (all LDG fully coalesced) ========
    {   // LUT replicated 16x interleaved: entry e replica r at ull idx e*16+r
        const ull* src = (const ull*)tlut;
#pragma unroll
        for (int k = tid; k < 8192; k += THREADS)
            lut[k] = src[k >> 4];               // broadcast LDG, coalesced STS
    }
    {   // trellis: 2048 int4 flat (t1 then t2), swizzled store
        const int4* t1v = (const int4*)trellis1 + (size_t)mo * 1024;
        const int4* t2v = (const int4*)trellis2 + (size_t)mo * 1024;
#pragma unroll
        for (int f = tid; f < 2048; f += THREADS) {
            const int4 v = (f < 1024) ? t1v[f] : t2v[f - 1024];
            tre[swz(f)] = v;
        }
    }
    {   // x: 4096 float4 flat [b*1024 + c4], swizzled store
        const float4* xv = (const float4*)inp;
#pragma unroll
        for (int f = tid; f < 4096; f += THREADS)
            xs[swz(f)] = xv[f];
    }
    __syncthreads();

    // ======== per-thread gathers from smem (conflict-free LDS.128) ========
    // trellis block ko, words packed per row: p[tx] = (w[2tx]<<16)|w[2tx+1]
    uint32_t p[16];
#pragma unroll
    for (int q = 0; q < 8; q++) {
        const int4 v = tre[ko * 8 + (q ^ (ko & 7))];
        p[2 * q + 0] = (((uint32_t)v.x & 0xFFFFu) << 16) | ((uint32_t)v.y & 0xFFFFu);
        p[2 * q + 1] = (((uint32_t)v.z & 0xFFFFu) << 16) | ((uint32_t)v.w & 0xFFFFu);
    }
    // x for this thread's 8 global columns [ko*16+half*8, +8), 4 batches
    ull x2[4][4];
#pragma unroll
    for (int b = 0; b < 4; b++) {
#pragma unroll
        for (int q = 0; q < 2; q++) {
            const int f = b * 1024 + ko * 4 + half * 2 + q;
            const float4 v = xs[swz(f)];
            x2[b][2 * q + 0] = pack2(v.x, v.y);
            x2[b][2 * q + 1] = pack2(v.z, v.w);
        }
    }

    const uint32_t lut_lane = smem_u32(smem_raw) + (uint32_t)(lane & 15) * 8u;

    // Decode: idx[s] = 9-bit window ending at nibble s of the big-endian word
    // stream (L=16 state recurrence collapses to a sliding window).
    // half=1 ctx for row tx is p[tx]; half=0 ctx is funnel(p[tx], p[tx-1], 16).
    uint32_t pv = 0;

#pragma unroll
    for (int ph = 0; ph < 4; ph++) {            // rows ph*4 .. ph*4+3
        ull acc[4][4];
#pragma unroll
        for (int r = 0; r < 4; r++)
#pragma unroll
            for (int b = 0; b < 4; b++) acc[r][b] = 0ull;

#pragma unroll
        for (int rg = 0; rg < 2; rg++) {        // 2 rows per group: 8-deep MLP
            uint32_t av[8];
#pragma unroll
            for (int rr = 0; rr < 2; rr++) {
                const int tx = ph * 4 + rg * 2 + rr;
                const uint32_t ctx = half ? p[tx]
                                          : __funnelshift_l(p[tx], pv, 16);
                pv = p[tx];
#pragma unroll
                for (int t = 0; t < 4; t++)
                    av[rr * 4 + t] =
                        lut_lane + ((ctx >> (12 - 4 * t)) & 0x1FFu) * 128u;
            }
            ull wv[8];
#pragma unroll
            for (int j = 0; j < 8; j++) wv[j] = lds64(av[j]);   // batched

#pragma unroll
            for (int rr = 0; rr < 2; rr++) {
                const int r = rg * 2 + rr;
#pragma unroll
                for (int t = 0; t < 4; t++) {
                    const ull w2 = wv[rr * 4 + t];
                    fma2(acc[r][0], w2, x2[0][t]);
                    fma2(acc[r][1], w2, x2[1][t]);
                    fma2(acc[r][2], w2, x2[2][t]);
                    fma2(acc[r][3], w2, x2[3][t]);
                }
            }
        }

        // collapse packed partials, then value-rotating warp reduction:
        // 16 sums over 32 lanes -> 1 per lane (15 shfl) + closing xor-16 add.
        float v[16];
#pragma unroll
        for (int r = 0; r < 4; r++)
#pragma unroll
            for (int b = 0; b < 4; b++) v[r * 4 + b] = sum2(acc[r][b]);

#define ROUND(S, N) { _Pragma("unroll")                                   \
        for (int i = 0; i < (N) / 2; i++) {                               \
            const bool hi2 = (lane & (S)) != 0;                           \
            const float snd = hi2 ? v[i] : v[i + (N) / 2];                \
            const float kp  = hi2 ? v[i + (N) / 2] : v[i];                \
            v[i] = kp + __shfl_xor_sync(0xffffffffu, snd, (S));           \
        } }
        ROUND(1, 16) ROUND(2, 8) ROUND(4, 4) ROUND(8, 2)
#undef ROUND
        v[0] += __shfl_xor_sync(0xffffffffu, v[0], 16);

        // lane l (l<16) holds value index bitrev4(l) = r*4+b of this phase
        const int oi = ((lane & 1) << 3) | ((lane & 2) << 1)
                     | ((lane & 4) >> 1) | ((lane & 8) >> 3);
        if (lane < 16) red[warp * 64 + ph * 16 + oi] = v[0];
    }

    __syncthreads();

    // cross-warp combine: 64 outputs (16 rows x 4 batches), 16 warps each
    if (tid < 64) {
        float s = 0.f;
#pragma unroll
        for (int w = 0; w < 16; w++) s += red[w * 64 + tid];
        const int phx = tid >> 4;         // tid = ph*16 + r*4 + b
        const int r   = (tid >> 2) & 3;
        const int b   = tid & 3;
        out[(size_t)b * OUTF + mo * 16 + phx * 4 + r] = s;
    }
}

extern "C" void kernel_launch(void* const* d_in, const int* in_sizes, int n_in,
                              void* d_out, int out_size) {
    const float* inp  = (const float*)d_in[0];
    const int*   t1   = (const int*)d_in[1];
    const int*   t2   = (const int*)d_in[2];
    const float* tlut = (const float*)d_in[3];
    float*       out  = (float*)d_out;

    cudaFuncSetAttribute(tcq_kernel,
                         cudaFuncAttributeMaxDynamicSharedMemorySize,
                         SMEM_TOTAL);
    tcq_kernel<<<NBLK, THREADS, SMEM_TOTAL>>>(inp, t1, t2, tlut, out);
}

// round 8
// speedup vs baseline: 1.9000x; 1.2764x over previous
#include <cuda_runtime.h>
#include <cstdint>

typedef unsigned long long ull;

#define THREADS 512
#define OUTF 11008
#define INF 4096
#define NCTA 148                    /* persistent: one CTA per SM */
#define NBLK 688                    /* OUTF/16 row-blocks */

#define SMEM_LUT_BYTES (512*16*8)   /* 64KB: LUT replicated 16x, interleaved */
#define SMEM_TRE_BYTES (2048*16)    /* 32KB: 256 blocks x 8 int4, swizzled   */
#define SMEM_X_BYTES   (4096*16)    /* 64KB: full x, float4 flat, swizzled   */
#define SMEM_RED_BYTES (16*64*4)    /* 4KB */
#define TRE_OFF SMEM_LUT_BYTES
#define X_OFF   (TRE_OFF + SMEM_TRE_BYTES)
#define RED_OFF (X_OFF + SMEM_X_BYTES)
#define SMEM_TOTAL (RED_OFF + SMEM_RED_BYTES)   /* 167936 */

__device__ __forceinline__ uint32_t smem_u32(const void* p) {
    uint32_t a;
    asm("{ .reg .u64 t; cvta.to.shared.u64 t, %1; cvt.u32.u64 %0, t; }"
        : "=r"(a) : "l"(p));
    return a;
}
__device__ __forceinline__ ull pack2(float lo, float hi) {
    ull r; asm("mov.b64 %0, {%1,%2};" : "=l"(r) : "f"(lo), "f"(hi)); return r;
}
__device__ __forceinline__ void fma2(ull& acc, ull a, ull b) {
    asm("fma.rn.f32x2 %0, %1, %2, %0;" : "+l"(acc) : "l"(a), "l"(b));
}
__device__ __forceinline__ float sum2(ull v) {
    float a, b; asm("mov.b64 {%0,%1}, %2;" : "=f"(a), "=f"(b) : "l"(v));
    return a + b;
}
__device__ __forceinline__ ull lds64(uint32_t addr) {
    ull v; asm("ld.shared.b64 %0, [%1];" : "=l"(v) : "r"(addr));
    return v;
}
/* 16B-granularity XOR swizzle: conflict-free for both the coalesced store
   side and the strided per-thread read side. */
__device__ __forceinline__ int swz(int f) { return f ^ ((f >> 3) & 7); }

__global__ void __launch_bounds__(THREADS, 1)
tcq_kernel(const float* __restrict__ inp,
           const int* __restrict__ trellis1,
           const int* __restrict__ trellis2,
           const float* __restrict__ tlut,
           float* __restrict__ out)
{
    extern __shared__ char smem_raw[];
    ull*    lut = (ull*)smem_raw;
    int4*   tre = (int4*)(smem_raw + TRE_OFF);
    float4* xs  = (float4*)(smem_raw + X_OFF);
    float*  red = (float*)(smem_raw + RED_OFF);

    const int tid  = threadIdx.x;
    const int lane = tid & 31;
    const int warp = tid >> 5;
    const int bid  = blockIdx.x;
    const int ko   = tid & 255;     // trellis block within mo
    const int half = tid >> 8;      // 0: word 2tx (cols 0-7), 1: word 2tx+1 (cols 8-15)

    // ======== one-time staging (all LDG fully coalesced) ========
    {   // LUT replicated 16x interleaved: entry e replica r at ull idx e*16+r
        const ull* src = (const ull*)tlut;
#pragma unroll
        for (int k = tid; k < 8192; k += THREADS)
            lut[k] = src[k >> 4];               // broadcast LDG, coalesced STS
    }
    {   // x: 4096 float4 flat [b*1024 + c4], swizzled store
        const float4* xv = (const float4*)inp;
#pragma unroll
        for (int f = tid; f < 4096; f += THREADS)
            xs[swz(f)] = xv[f];
    }
    __syncthreads();

    // x for this thread's 8 global columns [ko*16+half*8, +8), 4 batches —
    // constant across all mo blocks.
    ull x2[4][4];
#pragma unroll
    for (int b = 0; b < 4; b++) {
#pragma unroll
        for (int q = 0; q < 2; q++) {
            const int f = b * 1024 + ko * 4 + half * 2 + q;
            const float4 v = xs[swz(f)];
            x2[b][2 * q + 0] = pack2(v.x, v.y);
            x2[b][2 * q + 1] = pack2(v.z, v.w);
        }
    }

    const uint32_t lut_lane = smem_u32(smem_raw) + (uint32_t)(lane & 15) * 8u;
    const int4* t1v = (const int4*)trellis1;
    const int4* t2v = (const int4*)trellis2;

    // prefetch trellis for first block into registers (coalesced flat)
    int4 pf[4];
    {
        const int mo = bid;
#pragma unroll
        for (int q = 0; q < 4; q++) {
            const int f = tid + q * THREADS;     // flat 0..2047
            pf[q] = (f < 1024) ? t1v[(size_t)mo * 1024 + f]
                               : t2v[(size_t)mo * 1024 + f - 1024];
        }
    }

    // ======== persistent loop over this CTA's mo blocks ========
    for (int mo = bid; mo < NBLK; mo += NCTA) {
        // store prefetched trellis (swizzled), then prefetch next block
#pragma unroll
        for (int q = 0; q < 4; q++)
            tre[swz(tid + q * THREADS)] = pf[q];
        __syncthreads();

        const int mon = mo + NCTA;
        if (mon < NBLK) {
#pragma unroll
            for (int q = 0; q < 4; q++) {
                const int f = tid + q * THREADS;
                pf[q] = (f < 1024) ? t1v[(size_t)mon * 1024 + f]
                                   : t2v[(size_t)mon * 1024 + f - 1024];
            }
        }

        // trellis block ko, packed per row: p[tx] = (w[2tx]<<16)|w[2tx+1]
        uint32_t p[16];
#pragma unroll
        for (int q = 0; q < 8; q++) {
            const int4 v = tre[ko * 8 + (q ^ (ko & 7))];
            p[2*q+0] = (((uint32_t)v.x & 0xFFFFu) << 16) | ((uint32_t)v.y & 0xFFFFu);
            p[2*q+1] = (((uint32_t)v.z & 0xFFFFu) << 16) | ((uint32_t)v.w & 0xFFFFu);
        }

        // Decode: idx[s] = 9-bit window ending at nibble s of the big-endian
        // word stream. half=1 ctx for row tx is p[tx]; half=0 ctx is
        // funnel(p[tx], p[tx-1], 16) with p[-1]=0.
        uint32_t pv = 0;

#pragma unroll
        for (int ph = 0; ph < 4; ph++) {        // rows ph*4 .. ph*4+3
            ull acc[4][4];
#pragma unroll
            for (int r = 0; r < 4; r++)
#pragma unroll
                for (int b = 0; b < 4; b++) acc[r][b] = 0ull;

#pragma unroll
            for (int rg = 0; rg < 2; rg++) {    // 2 rows/group: 8-deep MLP
                uint32_t av[8];
#pragma unroll
                for (int rr = 0; rr < 2; rr++) {
                    const int tx = ph * 4 + rg * 2 + rr;
                    const uint32_t ctx = half ? p[tx]
                                              : __funnelshift_l(p[tx], pv, 16);
                    pv = p[tx];
#pragma unroll
                    for (int t = 0; t < 4; t++)
                        av[rr*4+t] = lut_lane + ((ctx >> (12-4*t)) & 0x1FFu) * 128u;
                }
                ull wv[8];
#pragma unroll
                for (int j = 0; j < 8; j++) wv[j] = lds64(av[j]);

#pragma unroll
                for (int rr = 0; rr < 2; rr++) {
                    const int r = rg * 2 + rr;
#pragma unroll
                    for (int t = 0; t < 4; t++) {
                        const ull w2 = wv[rr*4+t];
                        fma2(acc[r][0], w2, x2[0][t]);
                        fma2(acc[r][1], w2, x2[1][t]);
                        fma2(acc[r][2], w2, x2[2][t]);
                        fma2(acc[r][3], w2, x2[3][t]);
                    }
                }
            }

            // collapse packed partials, then value-rotating warp reduction:
            // 16 sums over 32 lanes -> 1 per lane (15 shfl) + closing xor-16.
            float v[16];
#pragma unroll
            for (int r = 0; r < 4; r++)
#pragma unroll
                for (int b = 0; b < 4; b++) v[r*4+b] = sum2(acc[r][b]);

#define ROUND(S, N) { _Pragma("unroll")                                   \
            for (int i = 0; i < (N) / 2; i++) {                           \
                const bool hi2 = (lane & (S)) != 0;                       \
                const float snd = hi2 ? v[i] : v[i + (N) / 2];            \
                const float kp  = hi2 ? v[i + (N) / 2] : v[i];            \
                v[i] = kp + __shfl_xor_sync(0xffffffffu, snd, (S));       \
            } }
            ROUND(1, 16) ROUND(2, 8) ROUND(4, 4) ROUND(8, 2)
#undef ROUND
            v[0] += __shfl_xor_sync(0xffffffffu, v[0], 16);

            // lane l (l<16) holds value index bitrev4(l) = r*4+b of this phase
            const int oi = ((lane & 1) << 3) | ((lane & 2) << 1)
                         | ((lane & 4) >> 1) | ((lane & 8) >> 3);
            if (lane < 16) red[warp * 64 + ph * 16 + oi] = v[0];
        }

        __syncthreads();

        // cross-warp combine: 64 outputs (16 rows x 4 batches), 16 warps each
        if (tid < 64) {
            float s = 0.f;
#pragma unroll
            for (int w = 0; w < 16; w++) s += red[w * 64 + tid];
            const int phx = tid >> 4;     // tid = ph*16 + r*4 + b
            const int r   = (tid >> 2) & 3;
            const int b   = tid & 3;
            out[(size_t)b * OUTF + mo * 16 + phx * 4 + r] = s;
        }
        __syncthreads();   // red/tre reuse barrier for next block
    }
}

extern "C" void kernel_launch(void* const* d_in, const int* in_sizes, int n_in,
                              void* d_out, int out_size) {
    const float* inp  = (const float*)d_in[0];
    const int*   t1   = (const int*)d_in[1];
    const int*   t2   = (const int*)d_in[2];
    const float* tlut = (const float*)d_in[3];
    float*       out  = (float*)d_out;

    cudaFuncSetAttribute(tcq_kernel,
                         cudaFuncAttributeMaxDynamicSharedMemorySize,
                         SMEM_TOTAL);
    tcq_kernel<<<NCTA, THREADS, SMEM_TOTAL>>>(inp, t1, t2, tlut, out);
}

// round 9
// speedup vs baseline: 2.0602x; 1.0843x over previous
#include <cuda_runtime.h>
#include <cstdint>

typedef unsigned long long ull;

#define THREADS 512
#define OUTF 11008
#define INF 4096
#define NCTA 148                    /* persistent: one CTA per SM */
#define NBLK 688                    /* OUTF/16 row-blocks */

#define SMEM_LUT_BYTES (512*16*8)   /* 64KB: LUT replicated 16x, interleaved  */
#define SMEM_TRE_BYTES (2048*16)    /* 32KB per buffer: 256 blk x 8 int4 swz  */
#define SMEM_X_BYTES   (4096*16)    /* 64KB: full x, float4 flat, swizzled    */
#define SMEM_RED_BYTES (16*64*4)    /* 4KB per buffer */
#define TRE_OFF  SMEM_LUT_BYTES
#define X_OFF    (TRE_OFF + 2*SMEM_TRE_BYTES)
#define RED_OFF  (X_OFF + SMEM_X_BYTES)
#define SMEM_TOTAL (RED_OFF + 2*SMEM_RED_BYTES)   /* 204800 */

__device__ __forceinline__ uint32_t smem_u32(const void* p) {
    uint32_t a;
    asm("{ .reg .u64 t; cvta.to.shared.u64 t, %1; cvt.u32.u64 %0, t; }"
        : "=r"(a) : "l"(p));
    return a;
}
__device__ __forceinline__ ull pack2(float lo, float hi) {
    ull r; asm("mov.b64 %0, {%1,%2};" : "=l"(r) : "f"(lo), "f"(hi)); return r;
}
__device__ __forceinline__ void fma2(ull& acc, ull a, ull b) {
    asm("fma.rn.f32x2 %0, %1, %2, %0;" : "+l"(acc) : "l"(a), "l"(b));
}
__device__ __forceinline__ float sum2(ull v) {
    float a, b; asm("mov.b64 {%0,%1}, %2;" : "=f"(a), "=f"(b) : "l"(v));
    return a + b;
}
__device__ __forceinline__ ull lds64(uint32_t addr) {
    ull v; asm("ld.shared.b64 %0, [%1];" : "=l"(v) : "r"(addr));
    return v;
}
__device__ __forceinline__ void cp16(uint32_t dst, const void* src) {
    asm volatile("cp.async.cg.shared.global [%0], [%1], 16;"
                 :: "r"(dst), "l"(src));
}
__device__ __forceinline__ void cp_commit() {
    asm volatile("cp.async.commit_group;");
}
__device__ __forceinline__ void cp_wait0() {
    asm volatile("cp.async.wait_group 0;");
}
/* 16B-granularity XOR swizzle: conflict-free for both the coalesced store
   side and the strided per-thread read side. */
__device__ __forceinline__ int swz(int f) { return f ^ ((f >> 3) & 7); }

__global__ void __launch_bounds__(THREADS, 1)
tcq_kernel(const float* __restrict__ inp,
           const int* __restrict__ trellis1,
           const int* __restrict__ trellis2,
           const float* __restrict__ tlut,
           float* __restrict__ out)
{
    extern __shared__ char smem_raw[];
    ull*    lut = (ull*)smem_raw;
    float4* xs  = (float4*)(smem_raw + X_OFF);

    const int tid  = threadIdx.x;
    const int lane = tid & 31;
    const int warp = tid >> 5;
    const int bid  = blockIdx.x;
    const int ko   = tid & 255;     // trellis block within mo
    const int half = tid >> 8;      // 0: word 2tx (cols 0-7), 1: word 2tx+1

    const uint32_t smem_base = smem_u32(smem_raw);
    const uint32_t tre_base  = smem_base + TRE_OFF;
    float* const red0 = (float*)(smem_raw + RED_OFF);
    float* const red1 = (float*)(smem_raw + RED_OFF + SMEM_RED_BYTES);

    const int4* t1v = (const int4*)trellis1;
    const int4* t2v = (const int4*)trellis2;

    // issue trellis prefetch for first block into tre buffer 0 (L1-bypass)
    {
        const int mo = bid;
#pragma unroll
        for (int q = 0; q < 4; q++) {
            const int f = tid + q * THREADS;     // flat 0..2047
            const int4* src = (f < 1024) ? &t1v[(size_t)mo * 1024 + f]
                                         : &t2v[(size_t)mo * 1024 + f - 1024];
            cp16(tre_base + (uint32_t)swz(f) * 16u, src);
        }
        cp_commit();
    }

    // ======== one-time staging (overlapped with the cp.async above) ========
    {   // LUT replicated 16x interleaved: entry e replica r at ull idx e*16+r
        const ull* src = (const ull*)tlut;
#pragma unroll
        for (int k = tid; k < 8192; k += THREADS)
            lut[k] = src[k >> 4];
    }
    {   // x: 4096 float4 flat [b*1024 + c4], swizzled store
        const float4* xv = (const float4*)inp;
#pragma unroll
        for (int f = tid; f < 4096; f += THREADS)
            xs[swz(f)] = xv[f];
    }
    cp_wait0();
    __syncthreads();

    // x for this thread's 8 global columns [ko*16+half*8, +8), 4 batches —
    // constant across all mo blocks.
    ull x2[4][4];
#pragma unroll
    for (int b = 0; b < 4; b++) {
#pragma unroll
        for (int q = 0; q < 2; q++) {
            const int f = b * 1024 + ko * 4 + half * 2 + q;
            const float4 v = xs[swz(f)];
            x2[b][2 * q + 0] = pack2(v.x, v.y);
            x2[b][2 * q + 1] = pack2(v.z, v.w);
        }
    }

    const uint32_t lut_lane = smem_base + (uint32_t)(lane & 15) * 8u;

    // ======== persistent loop: 1 barrier per block, epilogue deferred ======
    int buf = 0, prev_mo = -1;
    for (int mo = bid; mo < NBLK; mo += NCTA) {
        // prefetch next block's trellis into the other buffer (background)
        const int mon = mo + NCTA;
        if (mon < NBLK) {
            const uint32_t dst = tre_base + (uint32_t)(buf ^ 1) * SMEM_TRE_BYTES;
#pragma unroll
            for (int q = 0; q < 4; q++) {
                const int f = tid + q * THREADS;
                const int4* src = (f < 1024) ? &t1v[(size_t)mon * 1024 + f]
                                             : &t2v[(size_t)mon * 1024 + f - 1024];
                cp16(dst + (uint32_t)swz(f) * 16u, src);
            }
        }
        cp_commit();

        // deferred cross-warp combine for the previous block (other red buf)
        if (prev_mo >= 0 && tid < 64) {
            const float* rp = (buf == 0) ? red1 : red0;
            float s = 0.f;
#pragma unroll
            for (int w = 0; w < 16; w++) s += rp[w * 64 + tid];
            const int phx = tid >> 4;     // tid = ph*16 + r*4 + b
            const int r   = (tid >> 2) & 3;
            const int b   = tid & 3;
            out[(size_t)b * OUTF + prev_mo * 16 + phx * 4 + r] = s;
        }

        // trellis block ko from tre[buf]: p[tx] = (w[2tx]<<16)|w[2tx+1]
        const int4* tre = (const int4*)(smem_raw + TRE_OFF
                                        + (size_t)buf * SMEM_TRE_BYTES);
        uint32_t p[16];
#pragma unroll
        for (int q = 0; q < 8; q++) {
            const int4 v = tre[ko * 8 + (q ^ (ko & 7))];
            p[2*q+0] = (((uint32_t)v.x & 0xFFFFu) << 16) | ((uint32_t)v.y & 0xFFFFu);
            p[2*q+1] = (((uint32_t)v.z & 0xFFFFu) << 16) | ((uint32_t)v.w & 0xFFFFu);
        }

        float* const red = (buf == 0) ? red0 : red1;

        // Decode: idx[s] = 9-bit window ending at nibble s of the big-endian
        // word stream. half=1 ctx for row tx is p[tx]; half=0 ctx is
        // funnel(p[tx], p[tx-1], 16) with p[-1]=0.
        uint32_t pv = 0;

#pragma unroll
        for (int ph = 0; ph < 4; ph++) {        // rows ph*4 .. ph*4+3
            ull acc[4][4];
#pragma unroll
            for (int r = 0; r < 4; r++)
#pragma unroll
                for (int b = 0; b < 4; b++) acc[r][b] = 0ull;

#pragma unroll
            for (int rg = 0; rg < 2; rg++) {    // 2 rows/group: 8-deep MLP
                uint32_t av[8];
#pragma unroll
                for (int rr = 0; rr < 2; rr++) {
                    const int tx = ph * 4 + rg * 2 + rr;
                    const uint32_t ctx = half ? p[tx]
                                              : __funnelshift_l(p[tx], pv, 16);
                    pv = p[tx];
#pragma unroll
                    for (int t = 0; t < 4; t++)
                        av[rr*4+t] = lut_lane + ((ctx >> (12-4*t)) & 0x1FFu) * 128u;
                }
                ull wv[8];
#pragma unroll
                for (int j = 0; j < 8; j++) wv[j] = lds64(av[j]);

#pragma unroll
                for (int rr = 0; rr < 2; rr++) {
                    const int r = rg * 2 + rr;
#pragma unroll
                    for (int t = 0; t < 4; t++) {
                        const ull w2 = wv[rr*4+t];
                        fma2(acc[r][0], w2, x2[0][t]);
                        fma2(acc[r][1], w2, x2[1][t]);
                        fma2(acc[r][2], w2, x2[2][t]);
                        fma2(acc[r][3], w2, x2[3][t]);
                    }
                }
            }

            // collapse packed partials, then value-rotating warp reduction:
            // 16 sums over 32 lanes -> 1 per lane (15 shfl) + closing xor-16.
            float v[16];
#pragma unroll
            for (int r = 0; r < 4; r++)
#pragma unroll
                for (int b = 0; b < 4; b++) v[r*4+b] = sum2(acc[r][b]);

#define ROUND(S, N) { _Pragma("unroll")                                   \
            for (int i = 0; i < (N) / 2; i++) {                           \
                const bool hi2 = (lane & (S)) != 0;                       \
                const float snd = hi2 ? v[i] : v[i + (N) / 2];            \
                const float kp  = hi2 ? v[i + (N) / 2] : v[i];            \
                v[i] = kp + __shfl_xor_sync(0xffffffffu, snd, (S));       \
            } }
            ROUND(1, 16) ROUND(2, 8) ROUND(4, 4) ROUND(8, 2)
#undef ROUND
            v[0] += __shfl_xor_sync(0xffffffffu, v[0], 16);

            // lane l (l<16) holds value index bitrev4(l) = r*4+b of this phase
            const int oi = ((lane & 1) << 3) | ((lane & 2) << 1)
                         | ((lane & 4) >> 1) | ((lane & 8) >> 3);
            if (lane < 16) red[warp * 64 + ph * 16 + oi] = v[0];
        }

        // single barrier per block: next tre buffer ready + red visible
        cp_wait0();
        __syncthreads();

        prev_mo = mo;
        buf ^= 1;
    }

    // final combine for the last block (red in buf^1 after the flip)
    if (tid < 64) {
        const float* rp = (buf == 0) ? red1 : red0;
        float s = 0.f;
#pragma unroll
        for (int w = 0; w < 16; w++) s += rp[w * 64 + tid];
        const int phx = tid >> 4;
        const int r   = (tid >> 2) & 3;
        const int b   = tid & 3;
        out[(size_t)b * OUTF + prev_mo * 16 + phx * 4 + r] = s;
    }
}

extern "C" void kernel_launch(void* const* d_in, const int* in_sizes, int n_in,
                              void* d_out, int out_size) {
    const float* inp  = (const float*)d_in[0];
    const int*   t1   = (const int*)d_in[1];
    const int*   t2   = (const int*)d_in[2];
    const float* tlut = (const float*)d_in[3];
    float*       out  = (float*)d_out;

    cudaFuncSetAttribute(tcq_kernel,
                         cudaFuncAttributeMaxDynamicSharedMemorySize,
                         SMEM_TOTAL);
    tcq_kernel<<<NCTA, THREADS, SMEM_TOTAL>>>(inp, t1, t2, tlut, out);
}